// round 1
// baseline (speedup 1.0000x reference)
#include <cuda_runtime.h>

#define EPSF 1e-5f

// Problem constants
#define NND 256        // nodes
#define DD  128        // node dim
#define HH  512        // hidden
#define NR  65536      // NND*NND edge rows

// -------- scratch (device globals: allocation-free rule) --------
__device__ float g_edges[NR * DD];   // 33.5 MB
__device__ float g_adj[NR];
__device__ float g_msgs[NR];
__device__ float g_nodes[NND * DD];
__device__ float g_P[NND * HH];
__device__ float g_Q[NND * HH];

// ---------------------------------------------------------------
__global__ void k_copy_nodes(const float* __restrict__ src) {
    int i = blockIdx.x * blockDim.x + threadIdx.x;
    if (i < NND * DD) g_nodes[i] = src[i];
}

// edges init: dist -> LN(dist*w+b) -> relu, plus adjacency
__global__ void k_init_edges(const float* __restrict__ coords,
                             const float* __restrict__ w, const float* __restrict__ b,
                             const float* __restrict__ gg, const float* __restrict__ bb) {
    int warp = threadIdx.x >> 5, lane = threadIdx.x & 31;
    int row = blockIdx.x * 8 + warp;
    int i = row >> 8, j = row & 255;
    float dx = coords[i*3+0] - coords[j*3+0];
    float dy = coords[i*3+1] - coords[j*3+1];
    float dz = coords[i*3+2] - coords[j*3+2];
    float sq = dx*dx + dy*dy + dz*dz;
    float dist = sq > 0.f ? sqrtf(sq) : 0.f;
    if (lane == 0) g_adj[row] = (dist < 10.f) ? 1.f : 0.f;
    float e[4]; float s = 0.f, ss = 0.f;
#pragma unroll
    for (int t = 0; t < 4; t++) {
        int d = lane + 32*t;
        e[t] = dist * w[d] + b[d];
        s += e[t]; ss += e[t]*e[t];
    }
#pragma unroll
    for (int o = 16; o; o >>= 1) {
        s  += __shfl_xor_sync(0xffffffffu, s, o);
        ss += __shfl_xor_sync(0xffffffffu, ss, o);
    }
    float mean = s * (1.f/128.f);
    float var  = ss * (1.f/128.f) - mean*mean;
    float rs   = rsqrtf(var + EPSF);
#pragma unroll
    for (int t = 0; t < 4; t++) {
        int d = lane + 32*t;
        float v = (e[t]-mean)*rs*gg[d] + bb[d];
        g_edges[row*DD + d] = fmaxf(v, 0.f);
    }
}

// msgs[i,j] = adj[i,j] * dot(edges[i,j,:], nodes[i,:])
__global__ void k_msgs() {
    int warp = threadIdx.x >> 5, lane = threadIdx.x & 31;
    int row = blockIdx.x * 8 + warp;
    int i = row >> 8;
    const float4* e4 = (const float4*)(g_edges + row*DD);
    const float4* n4 = (const float4*)(g_nodes + i*DD);
    float4 a = e4[lane], c = n4[lane];
    float s = a.x*c.x + a.y*c.y + a.z*c.z + a.w*c.w;
#pragma unroll
    for (int o = 16; o; o >>= 1) s += __shfl_xor_sync(0xffffffffu, s, o);
    if (lane == 0) g_msgs[row] = g_adj[row] * s;
}

// P = nodes @ W1e[128:256],  Q = nodes @ W1e[256:384]
__global__ void __launch_bounds__(512) k_pq(const float* __restrict__ Wp,
                                            const float* __restrict__ Wq) {
    __shared__ float xs[32 * 128];
    int tid = threadIdx.x;
    int r0 = blockIdx.x * 32;
    const float* W = blockIdx.y ? Wq : Wp;
    float* out = blockIdx.y ? g_Q : g_P;
    float4* xs4 = (float4*)xs;
    const float4* src = (const float4*)(g_nodes + r0*DD);
#pragma unroll
    for (int t = 0; t < 2; t++) xs4[tid + t*512] = src[tid + t*512];
    __syncthreads();
    float acc[32];
#pragma unroll
    for (int r = 0; r < 32; r++) acc[r] = 0.f;
    for (int k = 0; k < 128; k++) {
        float wv = W[k*HH + tid];
#pragma unroll
        for (int r = 0; r < 32; r++) acc[r] = fmaf(xs[r*128 + k], wv, acc[r]);
    }
#pragma unroll
    for (int r = 0; r < 32; r++) out[(r0+r)*HH + tid] = acc[r];
}

// ---------------------------------------------------------------
// Fused edge update: edges += relu(LN(edges@W1a + P[i] + Q[j] + b1)) @ W2 + b2
// BM=64 rows, full N=512, K=128. 512 threads.
__global__ void __launch_bounds__(512, 1) k_edge(
        const float* __restrict__ W1a, const float* __restrict__ b1,
        const float* __restrict__ gg,  const float* __restrict__ bb,
        const float* __restrict__ W2,  const float* __restrict__ b2) {
    extern __shared__ float sm[];
    float* As   = sm;               // 64*128  = 8192
    float* Bs   = As + 8192;        // 16*512  = 8192
    float* Hs   = Bs + 8192;        // 64*512  = 32768
    float* Ps   = Hs + 32768;       // 512
    float* redS = Ps + 512;         // 128
    float* redQ = redS + 128;       // 128

    const int tid  = threadIdx.x;
    const int row0 = blockIdx.x * 64;
    const int i    = row0 >> 8;
    const int j0   = row0 & 255;

    {   // load edges tile (also the residual source)
        const float4* src = (const float4*)(g_edges + row0*DD);
        float4* dst = (float4*)As;
#pragma unroll
        for (int t = 0; t < 4; t++) dst[tid + t*512] = src[tid + t*512];
    }
    Ps[tid] = g_P[i*HH + tid] + b1[tid];
    __syncthreads();

    const int tr = tid >> 6, tc = tid & 63;
    const int m0 = tr * 8,  c0 = tc * 8;
    float acc[8][8];
#pragma unroll
    for (int mm = 0; mm < 8; mm++)
#pragma unroll
        for (int nn = 0; nn < 8; nn++) acc[mm][nn] = 0.f;

    // GEMM1: y = edges @ W1a  (K=128, 8 k-tiles of 16)
    for (int kt = 0; kt < 8; kt++) {
        {
            const float4* w4 = (const float4*)(W1a + kt*8192);
            float4* dst = (float4*)Bs;
#pragma unroll
            for (int t = 0; t < 4; t++) dst[tid + t*512] = w4[tid + t*512];
        }
        __syncthreads();
#pragma unroll
        for (int k = 0; k < 16; k++) {
            float4 t0 = *(const float4*)&Bs[k*HH + c0];
            float4 t1 = *(const float4*)&Bs[k*HH + c0 + 4];
#pragma unroll
            for (int mm = 0; mm < 8; mm++) {
                float a = As[(m0+mm)*128 + kt*16 + k];
                acc[mm][0] = fmaf(a, t0.x, acc[mm][0]);
                acc[mm][1] = fmaf(a, t0.y, acc[mm][1]);
                acc[mm][2] = fmaf(a, t0.z, acc[mm][2]);
                acc[mm][3] = fmaf(a, t0.w, acc[mm][3]);
                acc[mm][4] = fmaf(a, t1.x, acc[mm][4]);
                acc[mm][5] = fmaf(a, t1.y, acc[mm][5]);
                acc[mm][6] = fmaf(a, t1.z, acc[mm][6]);
                acc[mm][7] = fmaf(a, t1.w, acc[mm][7]);
            }
        }
        __syncthreads();
    }

    // epilogue: add P[i]+b1 and Q[j], then LN stats per row
    const int warp = tid >> 5, lane = tid & 31;
#pragma unroll
    for (int mm = 0; mm < 8; mm++) {
        const float* Qr = g_Q + (j0 + m0 + mm)*HH + c0;
        float s = 0.f, ss = 0.f;
#pragma unroll
        for (int nn = 0; nn < 8; nn++) {
            float y = acc[mm][nn] + Ps[c0+nn] + Qr[nn];
            acc[mm][nn] = y; s += y; ss += y*y;
        }
#pragma unroll
        for (int o = 16; o; o >>= 1) {
            s  += __shfl_xor_sync(0xffffffffu, s, o);
            ss += __shfl_xor_sync(0xffffffffu, ss, o);
        }
        if (lane == 0) { redS[warp*8 + mm] = s; redQ[warp*8 + mm] = ss; }
    }
    __syncthreads();
#pragma unroll
    for (int mm = 0; mm < 8; mm++) {
        float s  = redS[(tr*2)*8 + mm] + redS[(tr*2+1)*8 + mm];
        float ss = redQ[(tr*2)*8 + mm] + redQ[(tr*2+1)*8 + mm];
        float mean = s * (1.f/512.f);
        float var  = ss * (1.f/512.f) - mean*mean;
        float rs   = rsqrtf(var + EPSF);
        float4 o0, o1;
        o0.x = fmaxf((acc[mm][0]-mean)*rs*gg[c0+0] + bb[c0+0], 0.f);
        o0.y = fmaxf((acc[mm][1]-mean)*rs*gg[c0+1] + bb[c0+1], 0.f);
        o0.z = fmaxf((acc[mm][2]-mean)*rs*gg[c0+2] + bb[c0+2], 0.f);
        o0.w = fmaxf((acc[mm][3]-mean)*rs*gg[c0+3] + bb[c0+3], 0.f);
        o1.x = fmaxf((acc[mm][4]-mean)*rs*gg[c0+4] + bb[c0+4], 0.f);
        o1.y = fmaxf((acc[mm][5]-mean)*rs*gg[c0+5] + bb[c0+5], 0.f);
        o1.z = fmaxf((acc[mm][6]-mean)*rs*gg[c0+6] + bb[c0+6], 0.f);
        o1.w = fmaxf((acc[mm][7]-mean)*rs*gg[c0+7] + bb[c0+7], 0.f);
        *(float4*)&Hs[(m0+mm)*HH + c0]     = o0;
        *(float4*)&Hs[(m0+mm)*HH + c0 + 4] = o1;
    }
    __syncthreads();

    // GEMM2: out = h @ W2 (K=512), + residual + b2
    const int tc2 = tid & 31, tr2 = tid >> 5;  // cols tc2*4, rows tr2*4..+3
    float acc2[4][4];
#pragma unroll
    for (int rr = 0; rr < 4; rr++)
#pragma unroll
        for (int cc = 0; cc < 4; cc++) acc2[rr][cc] = 0.f;
    for (int kt = 0; kt < 32; kt++) {
        ((float4*)Bs)[tid] = ((const float4*)(W2 + kt*2048))[tid];
        __syncthreads();
#pragma unroll
        for (int k = 0; k < 16; k++) {
            float4 w = *(const float4*)&Bs[k*128 + tc2*4];
#pragma unroll
            for (int rr = 0; rr < 4; rr++) {
                float hv = Hs[(tr2*4+rr)*HH + kt*16 + k];
                acc2[rr][0] = fmaf(hv, w.x, acc2[rr][0]);
                acc2[rr][1] = fmaf(hv, w.y, acc2[rr][1]);
                acc2[rr][2] = fmaf(hv, w.z, acc2[rr][2]);
                acc2[rr][3] = fmaf(hv, w.w, acc2[rr][3]);
            }
        }
        __syncthreads();
    }
#pragma unroll
    for (int rr = 0; rr < 4; rr++) {
        int rm = tr2*4 + rr;
        int c  = tc2*4;
        float4 o;
        o.x = acc2[rr][0] + As[rm*128 + c+0] + b2[c+0];
        o.y = acc2[rr][1] + As[rm*128 + c+1] + b2[c+1];
        o.z = acc2[rr][2] + As[rm*128 + c+2] + b2[c+2];
        o.w = acc2[rr][3] + As[rm*128 + c+3] + b2[c+3];
        *(float4*)&g_edges[(row0+rm)*DD + c] = o;
    }
}

// ---------------------------------------------------------------
// shared building blocks for the 32-row MLP kernels (node update / final)
template<int KD>
__device__ __forceinline__ void mlp_ln_relu_32(
        const float* Xs, float* Bs, float* Hs, float* redS, float* redQ,
        const float* __restrict__ W1, const float* __restrict__ b1,
        const float* __restrict__ gg, const float* __restrict__ bb) {
    const int tid = threadIdx.x;
    const int tr = tid >> 6, tc = tid & 63;
    const int m0 = tr * 4, c0 = tc * 8;
    float acc[4][8];
#pragma unroll
    for (int mm = 0; mm < 4; mm++)
#pragma unroll
        for (int nn = 0; nn < 8; nn++) acc[mm][nn] = 0.f;

    for (int kt = 0; kt < KD/16; kt++) {
        {
            const float4* w4 = (const float4*)(W1 + kt*8192);
            float4* dst = (float4*)Bs;
#pragma unroll
            for (int t = 0; t < 4; t++) dst[tid + t*512] = w4[tid + t*512];
        }
        __syncthreads();
#pragma unroll
        for (int k = 0; k < 16; k++) {
            float4 t0 = *(const float4*)&Bs[k*HH + c0];
            float4 t1 = *(const float4*)&Bs[k*HH + c0 + 4];
#pragma unroll
            for (int mm = 0; mm < 4; mm++) {
                float a = Xs[(m0+mm)*KD + kt*16 + k];
                acc[mm][0] = fmaf(a, t0.x, acc[mm][0]);
                acc[mm][1] = fmaf(a, t0.y, acc[mm][1]);
                acc[mm][2] = fmaf(a, t0.z, acc[mm][2]);
                acc[mm][3] = fmaf(a, t0.w, acc[mm][3]);
                acc[mm][4] = fmaf(a, t1.x, acc[mm][4]);
                acc[mm][5] = fmaf(a, t1.y, acc[mm][5]);
                acc[mm][6] = fmaf(a, t1.z, acc[mm][6]);
                acc[mm][7] = fmaf(a, t1.w, acc[mm][7]);
            }
        }
        __syncthreads();
    }
    const int warp = tid >> 5, lane = tid & 31;
#pragma unroll
    for (int mm = 0; mm < 4; mm++) {
        float s = 0.f, ss = 0.f;
#pragma unroll
        for (int nn = 0; nn < 8; nn++) {
            float y = acc[mm][nn] + b1[c0+nn];
            acc[mm][nn] = y; s += y; ss += y*y;
        }
#pragma unroll
        for (int o = 16; o; o >>= 1) {
            s  += __shfl_xor_sync(0xffffffffu, s, o);
            ss += __shfl_xor_sync(0xffffffffu, ss, o);
        }
        if (lane == 0) { redS[warp*4 + mm] = s; redQ[warp*4 + mm] = ss; }
    }
    __syncthreads();
#pragma unroll
    for (int mm = 0; mm < 4; mm++) {
        float s  = redS[(tr*2)*4 + mm] + redS[(tr*2+1)*4 + mm];
        float ss = redQ[(tr*2)*4 + mm] + redQ[(tr*2+1)*4 + mm];
        float mean = s * (1.f/512.f);
        float var  = ss * (1.f/512.f) - mean*mean;
        float rs   = rsqrtf(var + EPSF);
#pragma unroll
        for (int nn = 0; nn < 8; nn++) {
            int c = c0 + nn;
            float h = (acc[mm][nn]-mean)*rs*gg[c] + bb[c];
            Hs[(m0+mm)*HH + c] = fmaxf(h, 0.f);
        }
    }
    __syncthreads();
}

__device__ __forceinline__ void gemm2_32(const float* Hs, float* Bs,
                                         const float* __restrict__ W2,
                                         float acc2[2][4]) {
    const int tid = threadIdx.x;
    const int tc2 = tid & 31, tr2 = tid >> 5;  // cols tc2*4, rows tr2*2..+1
#pragma unroll
    for (int rr = 0; rr < 2; rr++)
#pragma unroll
        for (int cc = 0; cc < 4; cc++) acc2[rr][cc] = 0.f;
    for (int kt = 0; kt < 32; kt++) {
        ((float4*)Bs)[tid] = ((const float4*)(W2 + kt*2048))[tid];
        __syncthreads();
#pragma unroll
        for (int k = 0; k < 16; k++) {
            float4 w = *(const float4*)&Bs[k*128 + tc2*4];
#pragma unroll
            for (int rr = 0; rr < 2; rr++) {
                float hv = Hs[(tr2*2+rr)*HH + kt*16 + k];
                acc2[rr][0] = fmaf(hv, w.x, acc2[rr][0]);
                acc2[rr][1] = fmaf(hv, w.y, acc2[rr][1]);
                acc2[rr][2] = fmaf(hv, w.z, acc2[rr][2]);
                acc2[rr][3] = fmaf(hv, w.w, acc2[rr][3]);
            }
        }
        __syncthreads();
    }
}

// node update: nodes += relu(LN([nodes|msgs]@W1 + b1)) @ W2 + b2
__global__ void __launch_bounds__(512, 1) k_node(
        const float* __restrict__ W1, const float* __restrict__ b1,
        const float* __restrict__ gg, const float* __restrict__ bb,
        const float* __restrict__ W2, const float* __restrict__ b2) {
    extern __shared__ float sm[];
    float* Xs   = sm;            // 32*384 = 12288
    float* Bs   = Xs + 12288;    // 8192
    float* Hs   = Bs + 8192;     // 16384
    float* redS = Hs + 16384;    // 64
    float* redQ = redS + 64;     // 64
    const int tid = threadIdx.x;
    const int r0 = blockIdx.x * 32;
    float4* xs4 = (float4*)Xs;
    {
        const float4* nsrc = (const float4*)(g_nodes + r0*DD);
#pragma unroll
        for (int t = 0; t < 2; t++) {
            int idx = tid + t*512;            // < 1024
            int row = idx >> 5, c4 = idx & 31;
            xs4[row*96 + c4] = nsrc[idx];
        }
        const float4* msrc = (const float4*)(g_msgs + r0*256);
#pragma unroll
        for (int t = 0; t < 4; t++) {
            int idx = tid + t*512;            // < 2048
            int row = idx >> 6, c4 = idx & 63;
            xs4[row*96 + 32 + c4] = msrc[idx];
        }
    }
    __syncthreads();
    mlp_ln_relu_32<384>(Xs, Bs, Hs, redS, redQ, W1, b1, gg, bb);
    float acc2[2][4];
    gemm2_32(Hs, Bs, W2, acc2);
    const int tc2 = tid & 31, tr2 = tid >> 5;
#pragma unroll
    for (int rr = 0; rr < 2; rr++) {
        int rm = tr2*2 + rr;
        int c  = tc2*4;
        float4 o;
        o.x = acc2[rr][0] + Xs[rm*384 + c+0] + b2[c+0];
        o.y = acc2[rr][1] + Xs[rm*384 + c+1] + b2[c+1];
        o.z = acc2[rr][2] + Xs[rm*384 + c+2] + b2[c+2];
        o.w = acc2[rr][3] + Xs[rm*384 + c+3] + b2[c+3];
        *(float4*)&g_nodes[(r0+rm)*DD + c] = o;
    }
}

// final: nodes_out = relu(LN(nd@no1))@no2+b ; coords = relu(LN(no@sp1))@sp2+b
__global__ void __launch_bounds__(512, 1) k_final(
        const float* __restrict__ no1_w, const float* __restrict__ no1_b,
        const float* __restrict__ no_g,  const float* __restrict__ no_bt,
        const float* __restrict__ no2_w, const float* __restrict__ no2_b,
        const float* __restrict__ sp1_w, const float* __restrict__ sp1_b,
        const float* __restrict__ sp_g,  const float* __restrict__ sp_bt,
        const float* __restrict__ sp2_w, const float* __restrict__ sp2_b,
        float* __restrict__ out_nodes, float* __restrict__ out_coords) {
    extern __shared__ float sm[];
    float* Xs   = sm;            // 4096
    float* Bs   = Xs + 4096;     // 8192
    float* Hs   = Bs + 8192;     // 16384
    float* X2   = Hs + 16384;    // 4096
    float* redS = X2 + 4096;     // 64
    float* redQ = redS + 64;     // 64
    const int tid = threadIdx.x;
    const int r0 = blockIdx.x * 32;
    {
        const float4* src = (const float4*)(g_nodes + r0*DD);
        float4* d4 = (float4*)Xs;
#pragma unroll
        for (int t = 0; t < 2; t++) d4[tid + t*512] = src[tid + t*512];
    }
    __syncthreads();
    mlp_ln_relu_32<128>(Xs, Bs, Hs, redS, redQ, no1_w, no1_b, no_g, no_bt);
    float acc2[2][4];
    gemm2_32(Hs, Bs, no2_w, acc2);
    const int tc2 = tid & 31, tr2 = tid >> 5;
#pragma unroll
    for (int rr = 0; rr < 2; rr++) {
        int rm = tr2*2 + rr;
        int c  = tc2*4;
        float4 o;
        o.x = acc2[rr][0] + no2_b[c+0];
        o.y = acc2[rr][1] + no2_b[c+1];
        o.z = acc2[rr][2] + no2_b[c+2];
        o.w = acc2[rr][3] + no2_b[c+3];
        *(float4*)&out_nodes[(r0+rm)*DD + c] = o;
        *(float4*)&X2[rm*128 + c] = o;
    }
    __syncthreads();
    mlp_ln_relu_32<128>(X2, Bs, Hs, redS, redQ, sp1_w, sp1_b, sp_g, sp_bt);
    if (tid < 96) {
        int row = tid / 3, cc = tid % 3;
        float s = sp2_b[cc];
        for (int k = 0; k < 512; k++) s = fmaf(Hs[row*HH + k], sp2_w[k*3 + cc], s);
        out_coords[(r0+row)*3 + cc] = s;
    }
}

// ---------------------------------------------------------------
extern "C" void kernel_launch(void* const* d_in, const int* in_sizes, int n_in,
                              void* d_out, int out_size) {
    const float* nodes  = (const float*)d_in[0];
    const float* coords = (const float*)d_in[1];
    const float* ee_w   = (const float*)d_in[2];
    const float* ee_b   = (const float*)d_in[3];
    const float* ee_g   = (const float*)d_in[4];
    const float* ee_bt  = (const float*)d_in[5];
    const float* nu1_w  = (const float*)d_in[6];
    const float* nu1_b  = (const float*)d_in[7];
    const float* nu_g   = (const float*)d_in[8];
    const float* nu_bt  = (const float*)d_in[9];
    const float* nu2_w  = (const float*)d_in[10];
    const float* nu2_b  = (const float*)d_in[11];
    const float* eu1_w  = (const float*)d_in[12];
    const float* eu1_b  = (const float*)d_in[13];
    const float* eu_g   = (const float*)d_in[14];
    const float* eu_bt  = (const float*)d_in[15];
    const float* eu2_w  = (const float*)d_in[16];
    const float* eu2_b  = (const float*)d_in[17];
    const float* sp1_w  = (const float*)d_in[18];
    const float* sp1_b  = (const float*)d_in[19];
    const float* sp_g   = (const float*)d_in[20];
    const float* sp_bt  = (const float*)d_in[21];
    const float* sp2_w  = (const float*)d_in[22];
    const float* sp2_b  = (const float*)d_in[23];
    const float* no1_w  = (const float*)d_in[24];
    const float* no1_b  = (const float*)d_in[25];
    const float* no_g   = (const float*)d_in[26];
    const float* no_bt  = (const float*)d_in[27];
    const float* no2_w  = (const float*)d_in[28];
    const float* no2_b  = (const float*)d_in[29];
    float* out = (float*)d_out;

    const int SME = (8192 + 8192 + 32768 + 512 + 128 + 128) * 4;   // 199680 B
    const int SMN = (12288 + 8192 + 16384 + 64 + 64) * 4;          // 147968 B
    const int SMF = (4096 + 8192 + 16384 + 4096 + 64 + 64) * 4;    // 131584 B
    cudaFuncSetAttribute(k_edge,  cudaFuncAttributeMaxDynamicSharedMemorySize, SME);
    cudaFuncSetAttribute(k_node,  cudaFuncAttributeMaxDynamicSharedMemorySize, SMN);
    cudaFuncSetAttribute(k_final, cudaFuncAttributeMaxDynamicSharedMemorySize, SMF);

    k_copy_nodes<<<64, 512>>>(nodes);
    k_init_edges<<<8192, 256>>>(coords, ee_w, ee_b, ee_g, ee_bt);

    for (int l = 0; l < 4; l++) {
        k_msgs<<<8192, 256>>>();
        k_pq<<<dim3(8, 2), 512>>>(eu1_w + l*196608 + 65536,   // W1e[128:256]
                                  eu1_w + l*196608 + 131072); // W1e[256:384]
        k_edge<<<1024, 512, SME>>>(eu1_w + l*196608, eu1_b + l*512,
                                   eu_g + l*512, eu_bt + l*512,
                                   eu2_w + l*65536, eu2_b + l*128);
        k_node<<<8, 512, SMN>>>(nu1_w + l*196608, nu1_b + l*512,
                                nu_g + l*512, nu_bt + l*512,
                                nu2_w + l*65536, nu2_b + l*128);
    }
    k_final<<<8, 512, SMF>>>(no1_w, no1_b, no_g, no_bt, no2_w, no2_b,
                             sp1_w, sp1_b, sp_g, sp_bt, sp2_w, sp2_b,
                             out, out + 32768);
}